// round 15
// baseline (speedup 1.0000x reference)
#include <cuda_runtime.h>
#include <cuda_fp16.h>
#include <cstdint>

#define Vn 55
#define Cn 64
#define Dn 64
#define Tn 128
#define Nn 64
#define NTn 8192
#define VD 3520

#define RS 72                  // padded row stride in fp16 elements (36 words)

// g fp16, padded rows: [n][c][t][64]  (row = 128 B, always 16B-aligned)
__device__ __half g_buf[(size_t)Nn * Cn * Tn * 64];
__device__ float2 d_mP[2048];             // mask pairs: [kp*64+u]
__device__ float2 d_AB1[4096];            // BN1 (scale, shift) packed, [d*64+u]
__device__ float d_A2[Dn];
__device__ float d_B2[Dn];
__device__ __half d_WhH[64 * RS];         // W^T fp16, [d*RS + c]

__device__ __forceinline__ void mma16(float* c, const unsigned* a, const unsigned* b) {
    asm volatile(
        "mma.sync.aligned.m16n8k16.row.col.f32.f16.f16.f32 "
        "{%0,%1,%2,%3}, {%4,%5,%6,%7}, {%8,%9}, {%0,%1,%2,%3};"
        : "+f"(c[0]), "+f"(c[1]), "+f"(c[2]), "+f"(c[3])
        : "r"(a[0]), "r"(a[1]), "r"(a[2]), "r"(a[3]), "r"(b[0]), "r"(b[1]));
}

// ---- prep: one-time tables -------------------------------------------------
__global__ __launch_bounds__(256) void prep_kernel(
    const float* __restrict__ W, const float* __restrict__ b,
    const float* __restrict__ fm,
    const float* __restrict__ g1, const float* __restrict__ be1,
    const float* __restrict__ m1, const float* __restrict__ v1,
    const float* __restrict__ g2, const float* __restrict__ be2,
    const float* __restrict__ m2, const float* __restrict__ v2)
{
    int i = blockIdx.x * 256 + threadIdx.x;   // 0..4095
    if (i < 2048) {
        int kp = i >> 6, u = i & 63;
        float m0 = 0.0f, m1v = 0.0f;
        if (u < Vn) {
            m0 = tanhf(fm[u * Cn + 2 * kp]) + 1.0f;
            m1v = tanhf(fm[u * Cn + 2 * kp + 1]) + 1.0f;
        }
        d_mP[i] = make_float2(m0, m1v);
    }
    if (i < 4096) {
        // W^T fp16, padded rows: i = c*64+d
        int c = i >> 6, d = i & 63;
        d_WhH[d * RS + c] = __float2half(W[i]);

        // BN1 packed: i = u*64+d -> store at [d*64+u]
        int u = i >> 6, dd = i & 63;
        float a = g1[i] * rsqrtf(v1[i] + 1e-5f);
        d_AB1[dd * 64 + u] = make_float2(a, be1[i] + a * (b[dd] - m1[i]));
    }
    if (i < Dn) {
        float a = g2[i] * rsqrtf(v2[i] + 1e-5f);
        d_A2[i] = a;
        d_B2[i] = be2[i] - a * m2[i];
    }
}

// ---- kernelA: shift+mask -> fp16 2-pass mma GEMM -> BN1+ReLU+inv shift -----
// Static smem 27648 B: AH[0,9216) AL[9216,18432) BH[18432,27648)
// Stage (4096 floats = 16384 B, 64-padded rows) overlays AH/AL after GEMM.
__global__ __launch_bounds__(256) void kernelA(const float* __restrict__ x)
{
    __shared__ __align__(16) char smraw[27648];
    __half* AH = (__half*)smraw;                 // [u*RS + k], swizzled
    __half* AL = AH + 64 * RS;
    __half* BH = AL + 64 * RS;                   // [d*RS + k]
    unsigned* AHw = (unsigned*)AH;
    unsigned* ALw = (unsigned*)AL;
    const unsigned* BHw = (const unsigned*)BH;

    const int tid = threadIdx.x;
    const int nt = blockIdx.x;
    const int n = nt >> 7;
    const int t = nt & 127;

    // Copy W tile (pre-converted): 9216 B = 576 float4
    {
        float4* bh4 = (float4*)BH;
        const float4* gh4 = (const float4*)d_WhH;
        for (int i = tid; i < 576; i += 256) bh4[i] = gh4[i];
    }

    // Build A: lanes span u (coalesced x reads), k-pair fixed per warp.
    const float* xnt = x + ((size_t)n * Cn * Tn + t) * Vn;
    for (int iw = tid; iw < 2048; iw += 256) {
        int u  = (iw & 31) + ((iw >> 10) << 5);
        int kp = (iw >> 5) & 31;
        int k  = kp << 1;
        float v0 = 0.0f, v1 = 0.0f;
        if (u < Vn) {
            int s0 = u + k;
            if (s0 >= Vn) s0 -= Vn;
            if (s0 >= Vn) s0 -= Vn;
            int s1 = s0 + 1;
            if (s1 >= Vn) s1 -= Vn;
            float2 m2v = d_mP[kp * 64 + u];
            v0 = xnt[(size_t)k * (Tn * Vn) + s0] * m2v.x;
            v1 = xnt[(size_t)(k + 1) * (Tn * Vn) + s1] * m2v.y;
        }
        __half2 h2 = __float22half2_rn(make_float2(v0, v1));
        float l0 = v0 - __half2float(__low2half(h2));
        float l1 = v1 - __half2float(__high2half(h2));
        __half2 l2 = __float22half2_rn(make_float2(l0, l1));
        int kws = kp ^ ((u >> 3) & 3);            // XOR swizzle
        AHw[u * 36 + kws] = *(unsigned*)&h2;
        ALw[u * 36 + kws] = *(unsigned*)&l2;
    }
    __syncthreads();

    // GEMM: y[u][d] = sum_k A[u][k] * WT[d][k].  M=64 N=64 K=64, 2 passes.
    const int w = tid >> 5;
    const int lane = tid & 31;
    const int lr = lane >> 2;
    const int lc = lane & 3;
    const int ub = (w & 3) * 16;
    const int nb = (w >> 2) * 32;
    const int row0 = ub + lr;
    const int row1 = row0 + 8;
    const int lcs0 = lc ^ ((row0 >> 3) & 3);
    const int lcs1 = lc ^ ((row1 >> 3) & 3);

    float acc[4][4];
#pragma unroll
    for (int i = 0; i < 4; i++)
#pragma unroll
        for (int j = 0; j < 4; j++) acc[i][j] = 0.0f;

#pragma unroll
    for (int s = 0; s < 4; s++) {               // k0 = s*16
        const int a0 = row0 * 36 + s * 8 + lcs0;
        const int a1 = row1 * 36 + s * 8 + lcs1;
        unsigned ah[4], al[4];
        ah[0] = AHw[a0];
        ah[1] = AHw[a1];
        ah[2] = AHw[a0 + 4];
        ah[3] = AHw[a1 + 4];
        al[0] = ALw[a0];
        al[1] = ALw[a1];
        al[2] = ALw[a0 + 4];
        al[3] = ALw[a1 + 4];
#pragma unroll
        for (int ntile = 0; ntile < 4; ntile++) {
            const int bbase = (nb + ntile * 8 + lr) * 36 + s * 8 + lc;
            unsigned bh[2];
            bh[0] = BHw[bbase];
            bh[1] = BHw[bbase + 4];
            mma16(acc[ntile], ah, bh);
            mma16(acc[ntile], al, bh);
        }
    }
    __syncthreads();   // GEMM smem reads done; A region becomes staging

    // Epilogue: BN1 + ReLU + inverse shift into stage[d*64 + (u+d)%55]
    float* stage = (float*)smraw;   // 4096 floats (64-padded rows)
#pragma unroll
    for (int i = 0; i < 4; i++) {
        int u = ub + lr + ((i & 2) ? 8 : 0);
        if (u < Vn) {
#pragma unroll
            for (int ntile = 0; ntile < 4; ntile++) {
                int d = nb + ntile * 8 + lc * 2 + (i & 1);
                float2 ab = d_AB1[d * 64 + u];
                float y = fmaxf(ab.x * acc[ntile][i] + ab.y, 0.0f);
                int vv = u + d;
                if (vv >= Vn) vv -= Vn;
                if (vv >= Vn) vv -= Vn;
                stage[d * 64 + vv] = y;
            }
        }
    }
    __syncthreads();

    // fp16 store to g[n][d][t][0..64): 128 B per row, uint4 writes
    for (int j = tid; j < 512; j += 256) {
        int d = j >> 3;
        int s = j & 7;
        const float4 fa = *(const float4*)(stage + d * 64 + s * 8);
        const float4 fb = *(const float4*)(stage + d * 64 + s * 8 + 4);
        __half2 p0 = __float22half2_rn(make_float2(fa.x, fa.y));
        __half2 p1 = __float22half2_rn(make_float2(fa.z, fa.w));
        __half2 p2 = __float22half2_rn(make_float2(fb.x, fb.y));
        __half2 p3 = __float22half2_rn(make_float2(fb.z, fb.w));
        uint4 u4 = make_uint4(*(unsigned*)&p0, *(unsigned*)&p1,
                              *(unsigned*)&p2, *(unsigned*)&p3);
        *(uint4*)(g_buf + (((size_t)(n * 64 + d)) * Tn + t) * 64 + s * 8) = u4;
    }
}

// ---- kernelB: one block per (n,c); g staged in smem, all gmem vectorized ---
__global__ __launch_bounds__(256) void kernelB(const float* __restrict__ x,
                                               float* __restrict__ out)
{
    __shared__ __align__(16) __half gs[Tn * 64];   // 16384 B

    const int nc = blockIdx.x;        // n*64 + c
    const int c = nc & 63;
    const int tid = threadIdx.x;

    // Stage all 128 g rows for this (n,c): 1024 uint4, fully linear
    {
        uint4* dst = (uint4*)gs;
        const uint4* src = (const uint4*)(g_buf + (size_t)nc * (Tn * 64));
        for (int j = tid; j < 1024; j += 256) dst[j] = src[j];
    }
    __syncthreads();

    const float a2 = d_A2[c];
    const float b2 = d_B2[c];
    const int off = (c % 3) - 1;
    const float* xb = x + (size_t)nc * 7040;
    float* ob = out + (size_t)nc * 7040;

    for (int j = tid; j < 1760; j += 256) {      // 1760 float4 groups
        int i0 = j * 4;
        int t = i0 / 55;
        int v = i0 - t * 55;
        float4 xv = *(const float4*)(xb + i0);
        float xr[4] = {xv.x, xv.y, xv.z, xv.w};
        float r[4];
#pragma unroll
        for (int e = 0; e < 4; e++) {
            int tt = t + off;
            float gv = 0.0f;
            if ((unsigned)tt < (unsigned)Tn) gv = __half2float(gs[tt * 64 + v]);
            r[e] = fmaxf(a2 * gv + b2 + xr[e], 0.0f);
            if (++v == 55) { v = 0; t++; }
        }
        *(float4*)(ob + i0) = make_float4(r[0], r[1], r[2], r[3]);
    }
}

extern "C" void kernel_launch(void* const* d_in, const int* in_sizes, int n_in,
                              void* d_out, int out_size)
{
    const float* x   = (const float*)d_in[0];
    const float* W   = (const float*)d_in[1];
    const float* b   = (const float*)d_in[2];
    const float* fm  = (const float*)d_in[3];
    const float* g1  = (const float*)d_in[4];
    const float* be1 = (const float*)d_in[5];
    const float* m1  = (const float*)d_in[6];
    const float* v1  = (const float*)d_in[7];
    const float* g2  = (const float*)d_in[8];
    const float* be2 = (const float*)d_in[9];
    const float* m2  = (const float*)d_in[10];
    const float* v2  = (const float*)d_in[11];
    float* out = (float*)d_out;

    prep_kernel<<<16, 256>>>(W, b, fm, g1, be1, m1, v1, g2, be2, m2, v2);
    kernelA<<<NTn, 256>>>(x);
    kernelB<<<Nn * Cn, 256>>>(x, out);
}